// round 12
// baseline (speedup 1.0000x reference)
#include <cuda_runtime.h>
#include <math.h>
#include <stdint.h>

#define BATCH 8
#define CH    192
#define C3    576
#define HH    128
#define WW    128
#define NPIX  16384
#define ORI   9
#define NHEAD 4
#define HDIM  48
#define NSPLIT 32
#define CGRP  16
#define CPG   (CH / CGRP)

#define PI_F 3.14159265358979323846f

// ---------------- scratch ----------------
__device__ float g_qkv [BATCH * C3 * NPIX];
__device__ float g_qkvd[BATCH * C3 * NPIX];
__device__ float g_xr  [BATCH * CH * NPIX];      // x pre-rounded to tf32 values
__device__ float g_wr  [C3 * CH];                // Wqkv pre-rounded
__device__ float g_hog9[BATCH * ORI * NPIX];
__device__ float g_sobp[BATCH * CGRP * 2 * NPIX];
__device__ float g_norms[BATCH * 2 * CH];
__device__ float g_npart[BATCH * 2 * CH * 4];
__device__ float g_spart[BATCH * NHEAD * NSPLIT * HDIM * HDIM];
__device__ float g_attn [BATCH * NHEAD * HDIM * HDIM];
__device__ float g_mb   [BATCH * CH * CH];

// ---------------- fast math (MUFU-free) ----------------
__device__ __forceinline__ float frcp_fast(float x) {
    float r = __uint_as_float(0x7EF311C3u - __float_as_uint(x));
    r = r * (2.f - x * r);
    r = r * (2.f - x * r);
    r = r * (2.f - x * r);
    return r;
}
__device__ __forceinline__ float fsqrt_fast(float x) {
    float r = __uint_as_float(0x5F3759DFu - (__float_as_uint(x) >> 1));
    r = r * (1.5f - 0.5f * x * r * r);
    r = r * (1.5f - 0.5f * x * r * r);
    return x * r;
}
__device__ __forceinline__ float fatan2_fast(float y, float x) {
    float ax = fabsf(x), ay = fabsf(y);
    float mx = fmaxf(ax, ay), mn = fminf(ax, ay);
    float t = mn * frcp_fast(fmaxf(mx, 1e-37f));
    float s = t * t;
    float p = -0.0117212f;
    p = fmaf(p, s,  0.05265332f);
    p = fmaf(p, s, -0.11643287f);
    p = fmaf(p, s,  0.19354346f);
    p = fmaf(p, s, -0.33262347f);
    p = fmaf(p, s,  0.99997726f);
    float a = t * p;
    a = (ay > ax) ? (1.57079632679f - a) : a;
    a = (x < 0.f) ? (3.14159265359f - a) : a;
    return copysignf(a, y);
}

// ---------------- tf32 / mma helpers ----------------
__device__ __forceinline__ float f2tf_f(float x) {
    uint32_t r; asm("cvt.rna.tf32.f32 %0, %1;" : "=r"(r) : "f"(x));
    return __uint_as_float(r);
}
__device__ __forceinline__ void mma_tf32(float& c0, float& c1, float& c2, float& c3,
                                         uint32_t a0, uint32_t a1, uint32_t a2, uint32_t a3,
                                         uint32_t b0, uint32_t b1) {
    asm volatile("mma.sync.aligned.m16n8k8.row.col.f32.tf32.tf32.f32 "
                 "{%0,%1,%2,%3}, {%4,%5,%6,%7}, {%8,%9}, {%0,%1,%2,%3};"
                 : "+f"(c0), "+f"(c1), "+f"(c2), "+f"(c3)
                 : "r"(a0), "r"(a1), "r"(a2), "r"(a3), "r"(b0), "r"(b1));
}
__device__ __forceinline__ void ldsm_x4(uint32_t& r0, uint32_t& r1, uint32_t& r2, uint32_t& r3,
                                        uint32_t addr) {
    asm volatile("ldmatrix.sync.aligned.m8n8.x4.shared.b16 {%0,%1,%2,%3}, [%4];"
                 : "=r"(r0), "=r"(r1), "=r"(r2), "=r"(r3) : "r"(addr));
}
__device__ __forceinline__ uint32_t smem_u32(const void* p) {
    uint32_t a;
    asm("{ .reg .u64 t; cvta.to.shared.u64 t, %1; cvt.u32.u64 %0, t; }" : "=r"(a) : "l"(p));
    return a;
}
__device__ __forceinline__ void cp16(uint32_t s, const float* g) {
    asm volatile("cp.async.cg.shared.global [%0], [%1], 16;" :: "r"(s), "l"(g));
}
#define CP_COMMIT() asm volatile("cp.async.commit_group;" ::: "memory")
#define CP_WAIT2()  asm volatile("cp.async.wait_group 2;" ::: "memory")

// ---------------- elementwise tf32 pre-round ----------------
__global__ __launch_bounds__(256)
void k_round(const float4* __restrict__ src, float4* __restrict__ dst)
{
    long i = (long)blockIdx.x * 256 + threadIdx.x;
    float4 v = src[i];
    dst[i] = make_float4(f2tf_f(v.x), f2tf_f(v.y), f2tf_f(v.z), f2tf_f(v.w));
}

// ---------------- Sobel ----------------
struct R6v { float v[6]; };
__device__ __forceinline__ R6v load_row_zero(const float* plane, int r, int w4) {
    R6v o;
    if (r < 0 || r >= HH) {
        #pragma unroll
        for (int i = 0; i < 6; i++) o.v[i] = 0.f;
        return o;
    }
    const float* p = plane + r * WW + w4;
    float4 c = *(const float4*)p;
    o.v[0] = (w4 > 0) ? p[-1] : 0.f;
    o.v[1] = c.x; o.v[2] = c.y; o.v[3] = c.z; o.v[4] = c.w;
    o.v[5] = (w4 + 4 < WW) ? p[4] : 0.f;
    return o;
}
__device__ __forceinline__ R6v load_row_rep(const float* plane, int r, int w4) {
    int rc = min(max(r, 0), HH - 1);
    const float* p = plane + rc * WW + w4;
    float4 c = *(const float4*)p;
    R6v o;
    o.v[1] = c.x; o.v[2] = c.y; o.v[3] = c.z; o.v[4] = c.w;
    o.v[0] = (w4 > 0) ? p[-1] : c.x;
    o.v[5] = (w4 + 4 < WW) ? p[4] : c.w;
    return o;
}

__global__ __launch_bounds__(128)
void k_sobel_part(const float* __restrict__ x)
{
    int strip = blockIdx.x;
    int b = blockIdx.y, g = blockIdx.z;
    int tid = threadIdx.x;
    int w4 = (tid & 31) * 4;
    int hb = strip * 16 + (tid >> 5) * 4;

    float as[4][4], ms[4][4];
    #pragma unroll
    for (int i = 0; i < 4; i++)
        #pragma unroll
        for (int j = 0; j < 4; j++) { as[i][j] = 0.f; ms[i][j] = 0.f; }

    int c0 = g * CPG;
    for (int c = c0; c < c0 + CPG; c++) {
        const float* plane = x + ((long)(b * CH + c)) * NPIX;
        R6v top = load_row_rep(plane, hb - 1, w4);
        R6v mid = load_row_rep(plane, hb,     w4);
        #pragma unroll
        for (int i = 0; i < 4; i++) {
            R6v bot = load_row_rep(plane, hb + 1 + i, w4);
            #pragma unroll
            for (int j = 0; j < 4; j++) {
                float tl = top.v[j], tm = top.v[j+1], tr = top.v[j+2];
                float ml = mid.v[j],                  mr = mid.v[j+2];
                float bl = bot.v[j], bm = bot.v[j+1], br = bot.v[j+2];
                float dx = ((tr - tl) + 2.f * (mr - ml) + (br - bl)) * 0.125f;
                float dy = ((bl - tl) + 2.f * (bm - tm) + (br - tr)) * 0.125f;
                ms[i][j] += fsqrt_fast(dx * dx + dy * dy + 1e-6f);
                as[i][j] += fatan2_fast(dy, dx + 1e-6f);
            }
            top = mid; mid = bot;
        }
    }

    float* ap = g_sobp + (long)((b * CGRP + g) * 2 + 0) * NPIX;
    float* mp = g_sobp + (long)((b * CGRP + g) * 2 + 1) * NPIX;
    #pragma unroll
    for (int i = 0; i < 4; i++) {
        int n = (hb + i) * WW + w4;
        *(float4*)&ap[n] = make_float4(as[i][0], as[i][1], as[i][2], as[i][3]);
        *(float4*)&mp[n] = make_float4(ms[i][0], ms[i][1], ms[i][2], ms[i][3]);
    }
}

__global__ void k_hogbin()
{
    int h = blockIdx.x, b = blockIdx.y, w = threadIdx.x;
    int n = h * WW + w;

    float a = 0.f, m = 0.f;
    #pragma unroll
    for (int g = 0; g < CGRP; g++) {
        a += g_sobp[((long)(b * CGRP + g) * 2 + 0) * NPIX + n];
        m += g_sobp[((long)(b * CGRP + g) * 2 + 1) * NPIX + n];
    }
    float mag = m * (1.f / (float)CH);
    float am  = a * (1.f / (float)CH);
    float ang = fmodf(am, PI_F);
    if (ang < 0.f) ang += PI_F;

    const float bw = PI_F / (float)ORI;
    const float ibw = (float)ORI / PI_F;
    #pragma unroll
    for (int o = 0; o < ORI; o++) {
        float ctr = ((float)o + 0.5f) * bw;
        float wt = fmaxf(1.f - fabsf(ang - ctr) * ibw, 0.f);
        g_hog9[(b * ORI + o) * NPIX + n] = wt * mag;
    }
}

// ---------------- TF32 mma GEMM: BM=192, BN=128, 512 thr (16 warps), 4-stage cp.async --
// Operands are PRE-ROUNDED to tf32 values; kernel copies raw bytes.
#define GBM 192
#define GBN 128
#define GBK 16
#define SAW 20
#define SB  136
#define STG 4
#define A_STG_B (GBM * SAW * 4)   // 15360
#define B_STG_B (GBK * SB * 4)    // 8704
#define GEMM_SMEM (STG * (A_STG_B + B_STG_B))   // 96256

__global__ __launch_bounds__(512, 1)
void k_gemm_tf32(const float* __restrict__ A, const float* __restrict__ B,
                 float* __restrict__ C, int M, int K, int N,
                 long aStr, long bStr, long cStr)
{
    extern __shared__ char dsm[];

    const float* Ab = A + (long)blockIdx.z * aStr;
    const float* Bb = B + (long)blockIdx.z * bStr;
    float*       Cb = C + (long)blockIdx.z * cStr;

    int m0 = blockIdx.y * GBM;
    int n0 = blockIdx.x * GBN;
    int tid = threadIdx.x, lane = tid & 31, warp = tid >> 5;
    int wm = warp & 3, wn = warp >> 2;   // 4 x 4 warps, each 48 x 32
    int fr = lane >> 2, fc = lane & 3;

    uint32_t smemBase = smem_u32(dsm);
    uint32_t aS[STG], bS[STG];
    #pragma unroll
    for (int s = 0; s < STG; s++) {
        aS[s] = smemBase + s * A_STG_B;
        bS[s] = smemBase + STG * A_STG_B + s * B_STG_B;
    }

    uint32_t aRowByte = (uint32_t)(((wm * 48 + (lane & 15)) * SAW + (lane >> 4) * 4) * 4);

    // A fill: 768 float4; threads 0..511 take id=tid, threads 0..255 also id=tid+512.
    int a_row0 = tid >> 2, a_kg0 = tid & 3;
    int a_row1 = (tid + 512) >> 2, a_kg1 = (tid + 512) & 3;
    bool a_has1 = tid < 256;
    // B fill: 512 float4, 1 per thread
    int b_k = tid >> 5, b_ng = tid & 31;

    #define FILL_STAGE(s, k0) do { \
        cp16(aS[s] + (uint32_t)((a_row0 * SAW + a_kg0 * 4) * 4), \
             Ab + (long)(m0 + a_row0) * K + (k0) + a_kg0 * 4); \
        if (a_has1) \
            cp16(aS[s] + (uint32_t)((a_row1 * SAW + a_kg1 * 4) * 4), \
                 Ab + (long)(m0 + a_row1) * K + (k0) + a_kg1 * 4); \
        cp16(bS[s] + (uint32_t)((b_k * SB + b_ng * 4) * 4), \
             Bb + (long)((k0) + b_k) * N + n0 + b_ng * 4); \
    } while (0)

    FILL_STAGE(0, 0);       CP_COMMIT();
    FILL_STAGE(1, GBK);     CP_COMMIT();
    FILL_STAGE(2, 2 * GBK); CP_COMMIT();

    float acc[3][4][4];
    #pragma unroll
    for (int mt = 0; mt < 3; mt++)
        #pragma unroll
        for (int nt = 0; nt < 4; nt++)
            #pragma unroll
            for (int j = 0; j < 4; j++) acc[mt][nt][j] = 0.f;

    int niter = K / GBK;
    for (int it = 0; it < niter; it++) {
        CP_WAIT2();
        __syncthreads();

        int s = it % STG;
        const float* Bp = (const float*)(dsm + STG * A_STG_B + s * B_STG_B);

        #pragma unroll
        for (int ks = 0; ks < 2; ks++) {
            uint32_t af[3][4], bf[4][2];
            #pragma unroll
            for (int mt = 0; mt < 3; mt++)
                ldsm_x4(af[mt][0], af[mt][1], af[mt][2], af[mt][3],
                        aS[s] + aRowByte + (uint32_t)((mt * 16 * SAW + ks * 8) * 4));
            #pragma unroll
            for (int nt = 0; nt < 4; nt++) {
                int n = wn * 32 + nt * 8 + fr;
                bf[nt][0] = __float_as_uint(Bp[(ks * 8 + fc) * SB + n]);
                bf[nt][1] = __float_as_uint(Bp[(ks * 8 + fc + 4) * SB + n]);
            }
            #pragma unroll
            for (int mt = 0; mt < 3; mt++)
                #pragma unroll
                for (int nt = 0; nt < 4; nt++)
                    mma_tf32(acc[mt][nt][0], acc[mt][nt][1], acc[mt][nt][2], acc[mt][nt][3],
                             af[mt][0], af[mt][1], af[mt][2], af[mt][3],
                             bf[nt][0], bf[nt][1]);
        }

        __syncthreads();   // all reads of stage (it%STG) done before refill below
        if (it + 3 < niter) FILL_STAGE((it + 3) % STG, (it + 3) * GBK);
        CP_COMMIT();       // empty group when no fill: keeps wait_group(2) invariant
    }

    #pragma unroll
    for (int mt = 0; mt < 3; mt++) {
        #pragma unroll
        for (int nt = 0; nt < 4; nt++) {
            int gm = m0 + wm * 48 + mt * 16 + fr;
            int gn = n0 + wn * 32 + nt * 8 + fc * 2;
            float2 lo = make_float2(acc[mt][nt][0], acc[mt][nt][1]);
            float2 hi = make_float2(acc[mt][nt][2], acc[mt][nt][3]);
            *(float2*)&Cb[(long)gm * N + gn] = lo;
            *(float2*)&Cb[(long)(gm + 8) * N + gn] = hi;
        }
    }
    #undef FILL_STAGE
}

// ---------------- depthwise 3x3 + HOG add + norm partials ----------------
// v-channel outputs are rounded to tf32 values at write (GEMM2 B operand).
__global__ __launch_bounds__(128)
void k_dwconv(const float* __restrict__ wdw, const float* __restrict__ whog)
{
    int strip = blockIdx.x;
    int ch = blockIdx.y, b = blockIdx.z;
    int tid = threadIdx.x;
    int w4 = (tid & 31) * 4;
    int hb = strip * 32 + (tid >> 5) * 8;

    const float* plane = g_qkv + ((long)(b * C3 + ch)) * NPIX;
    const float* kwp = wdw + ch * 9;
    float k00 = kwp[0], k01 = kwp[1], k02 = kwp[2];
    float k10 = kwp[3], k11 = kwp[4], k12 = kwp[5];
    float k20 = kwp[6], k21 = kwp[7], k22 = kwp[8];

    bool isv = (ch >= 2 * CH);
    float wh[ORI];
    if (isv) {
        int d = ch - 2 * CH;
        #pragma unroll
        for (int o = 0; o < ORI; o++) wh[o] = whog[d * ORI + o];
    }

    float* outp = g_qkvd + ((long)(b * C3 + ch)) * NPIX;
    const float* hogp = g_hog9 + (long)b * ORI * NPIX;

    R6v top = load_row_zero(plane, hb - 1, w4);
    R6v mid = load_row_zero(plane, hb,     w4);
    float ssq = 0.f;

    #pragma unroll
    for (int i = 0; i < 8; i++) {
        R6v bot = load_row_zero(plane, hb + 1 + i, w4);
        float o0, o1, o2, o3;
        o0 = top.v[0]*k00 + top.v[1]*k01 + top.v[2]*k02
           + mid.v[0]*k10 + mid.v[1]*k11 + mid.v[2]*k12
           + bot.v[0]*k20 + bot.v[1]*k21 + bot.v[2]*k22;
        o1 = top.v[1]*k00 + top.v[2]*k01 + top.v[3]*k02
           + mid.v[1]*k10 + mid.v[2]*k11 + mid.v[3]*k12
           + bot.v[1]*k20 + bot.v[2]*k21 + bot.v[3]*k22;
        o2 = top.v[2]*k00 + top.v[3]*k01 + top.v[4]*k02
           + mid.v[2]*k10 + mid.v[3]*k11 + mid.v[4]*k12
           + bot.v[2]*k20 + bot.v[3]*k21 + bot.v[4]*k22;
        o3 = top.v[3]*k00 + top.v[4]*k01 + top.v[5]*k02
           + mid.v[3]*k10 + mid.v[4]*k11 + mid.v[5]*k12
           + bot.v[3]*k20 + bot.v[4]*k21 + bot.v[5]*k22;

        int n = (hb + i) * WW + w4;
        if (isv) {
            #pragma unroll
            for (int o = 0; o < ORI; o++) {
                float4 h = *(const float4*)&hogp[(long)o * NPIX + n];
                o0 += wh[o] * h.x; o1 += wh[o] * h.y;
                o2 += wh[o] * h.z; o3 += wh[o] * h.w;
            }
            o0 = f2tf_f(o0); o1 = f2tf_f(o1); o2 = f2tf_f(o2); o3 = f2tf_f(o3);
        } else {
            ssq += o0*o0 + o1*o1 + o2*o2 + o3*o3;
        }
        *(float4*)&outp[n] = make_float4(o0, o1, o2, o3);
        top = mid; mid = bot;
    }

    if (!isv) {
        int lane = tid & 31, warp = tid >> 5;
        #pragma unroll
        for (int off = 16; off; off >>= 1) ssq += __shfl_xor_sync(0xffffffffu, ssq, off);
        __shared__ float red[4];
        if (lane == 0) red[warp] = ssq;
        __syncthreads();
        if (tid == 0)
            g_npart[(b * 2 * CH + ch) * 4 + strip] = red[0] + red[1] + red[2] + red[3];
    }
}

__global__ void k_norm2()
{
    int r = blockIdx.x, b = blockIdx.y, t = threadIdx.x;
    float v = (t < 4) ? g_npart[(b * 2 * CH + r) * 4 + t] : 0.f;
    #pragma unroll
    for (int off = 16; off; off >>= 1) v += __shfl_xor_sync(0xffffffffu, v, off);
    if (t == 0) g_norms[b * 2 * CH + r] = fmaxf(sqrtf(v), 1e-12f);
}

// ---------------- S partial = q . k^T ----------------
__global__ __launch_bounds__(256)
void k_spart()
{
    int sp = blockIdx.x, hh = blockIdx.y, b = blockIdx.z;
    int tid = threadIdx.x;
    __shared__ float qs[HDIM][65];
    __shared__ float ks[HDIM][65];

    const float* qp = g_qkvd + ((long)(b * C3 + hh * HDIM)) * NPIX;
    const float* kp = g_qkvd + ((long)(b * C3 + CH + hh * HDIM)) * NPIX;

    int c0 = (tid >> 4) * 3;
    int d0 = (tid & 15) * 3;
    float acc[3][3];
    #pragma unroll
    for (int i = 0; i < 3; i++)
        #pragma unroll
        for (int j = 0; j < 3; j++) acc[i][j] = 0.f;

    int nbase = sp * (NPIX / NSPLIT);
    for (int chunk = 0; chunk < 8; chunk++) {
        int n0 = nbase + chunk * 64;
        __syncthreads();
        #pragma unroll
        for (int l = 0; l < 12; l++) {
            int e = l * 256 + tid;
            int c = e >> 6, nn = e & 63;
            qs[c][nn] = qp[(long)c * NPIX + n0 + nn];
            ks[c][nn] = kp[(long)c * NPIX + n0 + nn];
        }
        __syncthreads();
        #pragma unroll 16
        for (int nn = 0; nn < 64; nn++) {
            float a0 = qs[c0][nn], a1 = qs[c0 + 1][nn], a2 = qs[c0 + 2][nn];
            float b0 = ks[d0][nn], b1 = ks[d0 + 1][nn], b2 = ks[d0 + 2][nn];
            acc[0][0] += a0 * b0; acc[0][1] += a0 * b1; acc[0][2] += a0 * b2;
            acc[1][0] += a1 * b0; acc[1][1] += a1 * b1; acc[1][2] += a1 * b2;
            acc[2][0] += a2 * b0; acc[2][1] += a2 * b1; acc[2][2] += a2 * b2;
        }
    }

    float* op = g_spart + (((long)(b * NHEAD + hh) * NSPLIT + sp) * HDIM) * HDIM;
    #pragma unroll
    for (int i = 0; i < 3; i++)
        #pragma unroll
        for (int j = 0; j < 3; j++)
            op[(c0 + i) * HDIM + d0 + j] = acc[i][j];
}

__global__ void k_softmax(const float* __restrict__ temp)
{
    int hh = blockIdx.x, b = blockIdx.y, tid = threadIdx.x;
    __shared__ float sS[HDIM][HDIM];
    float tv = temp[hh];

    const float* base = g_spart + (long)(b * NHEAD + hh) * NSPLIT * HDIM * HDIM;
    for (int e = tid; e < HDIM * HDIM; e += 256) {
        float s = 0.f;
        for (int sp = 0; sp < NSPLIT; sp++) s += base[sp * HDIM * HDIM + e];
        int c = e / HDIM, d = e % HDIM;
        float nq = g_norms[b * 2 * CH + hh * HDIM + c];
        float nk = g_norms[b * 2 * CH + CH + hh * HDIM + d];
        sS[c][d] = s * tv / (nq * nk);
    }
    __syncthreads();

    int warp = tid >> 5, lane = tid & 31;
    for (int r = warp; r < HDIM; r += 8) {
        float v0 = sS[r][lane];
        float v1 = (lane + 32 < HDIM) ? sS[r][lane + 32] : -3.4e38f;
        float m = fmaxf(v0, v1);
        #pragma unroll
        for (int off = 16; off; off >>= 1) m = fmaxf(m, __shfl_xor_sync(0xffffffffu, m, off));
        float e0 = expf(v0 - m);
        float e1 = (lane + 32 < HDIM) ? expf(v1 - m) : 0.f;
        float s = e0 + e1;
        #pragma unroll
        for (int off = 16; off; off >>= 1) s += __shfl_xor_sync(0xffffffffu, s, off);
        float inv = 1.f / s;
        float* op = g_attn + ((long)(b * NHEAD + hh) * HDIM + r) * HDIM;
        op[lane] = e0 * inv;
        if (lane + 32 < HDIM) op[lane + 32] = e1 * inv;
    }
}

// Mb rounded to tf32 values at write (GEMM2 A operand)
__global__ void k_mb(const float* __restrict__ wproj)
{
    int d = blockIdx.x, b = blockIdx.y, e = threadIdx.x;
    int hh = d / HDIM, dl = d % HDIM;
    __shared__ float acol[HDIM];
    if (e < HDIM) acol[e] = g_attn[((long)(b * NHEAD + hh) * HDIM + e) * HDIM + dl];
    __syncthreads();
    const float* wp = wproj + e * CH + hh * HDIM;
    float s = 0.f;
    #pragma unroll
    for (int c = 0; c < HDIM; c++) s += wp[c] * acol[c];
    g_mb[((long)(b * CH + e)) * CH + d] = f2tf_f(s);
}

// ---------------- launch ----------------
extern "C" void kernel_launch(void* const* d_in, const int* in_sizes, int n_in,
                              void* d_out, int out_size)
{
    const float* x     = (const float*)d_in[0];
    const float* Wqkv  = (const float*)d_in[1];
    const float* Wdw   = (const float*)d_in[2];
    const float* Whog  = (const float*)d_in[3];
    const float* Wproj = (const float*)d_in[4];
    const float* temp  = (const float*)d_in[5];
    float* out = (float*)d_out;

    float *p_qkv, *p_qkvd, *p_mb, *p_xr, *p_wr;
    cudaGetSymbolAddress((void**)&p_qkv,  g_qkv);
    cudaGetSymbolAddress((void**)&p_qkvd, g_qkvd);
    cudaGetSymbolAddress((void**)&p_mb,   g_mb);
    cudaGetSymbolAddress((void**)&p_xr,   g_xr);
    cudaGetSymbolAddress((void**)&p_wr,   g_wr);

    cudaFuncSetAttribute(k_gemm_tf32, cudaFuncAttributeMaxDynamicSharedMemorySize, GEMM_SMEM);

    // launches 0-2 (GEMM1 stays at capture index 3)
    k_round<<<(BATCH * CH * NPIX) / 4 / 256, 256>>>((const float4*)x, (float4*)p_xr);
    k_sobel_part<<<dim3(8, BATCH, CGRP), 128>>>(x);
    k_round<<<(C3 * CH) / 4 / 256, 256>>>((const float4*)Wqkv, (float4*)p_wr);

    // launch 3: QKV 1x1 conv (tf32 mma, 512-thread 4-stage cp.async)
    k_gemm_tf32<<<dim3(NPIX / GBN, C3 / GBM, BATCH), 512, GEMM_SMEM>>>(
        p_wr, p_xr, p_qkv, C3, CH, NPIX,
        0L, (long)CH * NPIX, (long)C3 * NPIX);

    // HOG bins (needed before dwconv)
    k_hogbin<<<dim3(HH, BATCH), WW>>>();

    // depthwise 3x3 + HOG add + norm partials (v rounded at write)
    k_dwconv<<<dim3(4, C3, BATCH), 128>>>(Wdw, Whog);

    // finalize q/k norms
    k_norm2<<<dim3(2 * CH, BATCH), 32>>>();

    // S partials
    k_spart<<<dim3(NSPLIT, NHEAD, BATCH), 256>>>();

    // softmax
    k_softmax<<<dim3(NHEAD, BATCH), 256>>>(temp);

    // Mb = W_proj @ blockdiag(attn)  (rounded at write)
    k_mb<<<dim3(CH, BATCH), CH>>>(Wproj);

    // out = Mb @ v (tf32 mma, 512-thread 4-stage cp.async)
    k_gemm_tf32<<<dim3(NPIX / GBN, CH / GBM, BATCH), 512, GEMM_SMEM>>>(
        p_mb, p_qkvd + (long)2 * CH * NPIX, out, CH, CH, NPIX,
        (long)CH * CH, (long)C3 * NPIX, (long)CH * NPIX);
}

// round 14
// speedup vs baseline: 1.1702x; 1.1702x over previous
#include <cuda_runtime.h>
#include <math.h>
#include <stdint.h>

#define BATCH 8
#define CH    192
#define C3    576
#define HH    128
#define WW    128
#define NPIX  16384
#define ORI   9
#define NHEAD 4
#define HDIM  48
#define NSPLIT 32
#define CGRP  16
#define CPG   (CH / CGRP)

#define PI_F 3.14159265358979323846f

// ---------------- scratch ----------------
__device__ float g_qkv [BATCH * C3 * NPIX];
__device__ float g_qkvd[BATCH * C3 * NPIX];
__device__ float g_xr  [BATCH * CH * NPIX];      // x pre-rounded to tf32 (written by sobel)
__device__ float g_wr  [C3 * CH];                // Wqkv pre-rounded
__device__ float g_hog9[BATCH * ORI * NPIX];
__device__ float g_sobp[BATCH * CGRP * 2 * NPIX];
__device__ float g_norms[BATCH * 2 * CH];
__device__ float g_npart[BATCH * 2 * CH * 4];
__device__ float g_spart[BATCH * NHEAD * NSPLIT * HDIM * HDIM];
__device__ float g_attn [BATCH * NHEAD * HDIM * HDIM];
__device__ float g_mb   [BATCH * CH * CH];

// ---------------- fast math (MUFU-free) ----------------
__device__ __forceinline__ float frcp_fast(float x) {
    float r = __uint_as_float(0x7EF311C3u - __float_as_uint(x));
    r = r * (2.f - x * r);
    r = r * (2.f - x * r);
    r = r * (2.f - x * r);
    return r;
}
__device__ __forceinline__ float fsqrt_fast(float x) {
    float r = __uint_as_float(0x5F3759DFu - (__float_as_uint(x) >> 1));
    r = r * (1.5f - 0.5f * x * r * r);
    r = r * (1.5f - 0.5f * x * r * r);
    return x * r;
}
__device__ __forceinline__ float fatan2_fast(float y, float x) {
    float ax = fabsf(x), ay = fabsf(y);
    float mx = fmaxf(ax, ay), mn = fminf(ax, ay);
    float t = mn * frcp_fast(fmaxf(mx, 1e-37f));
    float s = t * t;
    float p = -0.0117212f;
    p = fmaf(p, s,  0.05265332f);
    p = fmaf(p, s, -0.11643287f);
    p = fmaf(p, s,  0.19354346f);
    p = fmaf(p, s, -0.33262347f);
    p = fmaf(p, s,  0.99997726f);
    float a = t * p;
    a = (ay > ax) ? (1.57079632679f - a) : a;
    a = (x < 0.f) ? (3.14159265359f - a) : a;
    return copysignf(a, y);
}

// ---------------- tf32 / mma helpers ----------------
__device__ __forceinline__ float f2tf_f(float x) {
    uint32_t r; asm("cvt.rna.tf32.f32 %0, %1;" : "=r"(r) : "f"(x));
    return __uint_as_float(r);
}
__device__ __forceinline__ void mma_tf32(float& c0, float& c1, float& c2, float& c3,
                                         uint32_t a0, uint32_t a1, uint32_t a2, uint32_t a3,
                                         uint32_t b0, uint32_t b1) {
    asm volatile("mma.sync.aligned.m16n8k8.row.col.f32.tf32.tf32.f32 "
                 "{%0,%1,%2,%3}, {%4,%5,%6,%7}, {%8,%9}, {%0,%1,%2,%3};"
                 : "+f"(c0), "+f"(c1), "+f"(c2), "+f"(c3)
                 : "r"(a0), "r"(a1), "r"(a2), "r"(a3), "r"(b0), "r"(b1));
}
__device__ __forceinline__ void ldsm_x4(uint32_t& r0, uint32_t& r1, uint32_t& r2, uint32_t& r3,
                                        uint32_t addr) {
    asm volatile("ldmatrix.sync.aligned.m8n8.x4.shared.b16 {%0,%1,%2,%3}, [%4];"
                 : "=r"(r0), "=r"(r1), "=r"(r2), "=r"(r3) : "r"(addr));
}
__device__ __forceinline__ uint32_t smem_u32(const void* p) {
    uint32_t a;
    asm("{ .reg .u64 t; cvta.to.shared.u64 t, %1; cvt.u32.u64 %0, t; }" : "=r"(a) : "l"(p));
    return a;
}
__device__ __forceinline__ void cp16(uint32_t s, const float* g) {
    asm volatile("cp.async.cg.shared.global [%0], [%1], 16;" :: "r"(s), "l"(g));
}
#define CP_COMMIT() asm volatile("cp.async.commit_group;" ::: "memory")
#define CP_WAIT1()  asm volatile("cp.async.wait_group 1;" ::: "memory")

// ---------------- elementwise tf32 pre-round (weights only) ----------------
__global__ __launch_bounds__(256)
void k_round(const float4* __restrict__ src, float4* __restrict__ dst)
{
    long i = (long)blockIdx.x * 256 + threadIdx.x;
    float4 v = src[i];
    dst[i] = make_float4(f2tf_f(v.x), f2tf_f(v.y), f2tf_f(v.z), f2tf_f(v.w));
}

// ---------------- Sobel (+ fused tf32 rounding of x into g_xr) ----------------
struct R6v { float v[6]; };
__device__ __forceinline__ R6v load_row_zero(const float* plane, int r, int w4) {
    R6v o;
    if (r < 0 || r >= HH) {
        #pragma unroll
        for (int i = 0; i < 6; i++) o.v[i] = 0.f;
        return o;
    }
    const float* p = plane + r * WW + w4;
    float4 c = *(const float4*)p;
    o.v[0] = (w4 > 0) ? p[-1] : 0.f;
    o.v[1] = c.x; o.v[2] = c.y; o.v[3] = c.z; o.v[4] = c.w;
    o.v[5] = (w4 + 4 < WW) ? p[4] : 0.f;
    return o;
}
__device__ __forceinline__ R6v load_row_rep(const float* plane, int r, int w4) {
    int rc = min(max(r, 0), HH - 1);
    const float* p = plane + rc * WW + w4;
    float4 c = *(const float4*)p;
    R6v o;
    o.v[1] = c.x; o.v[2] = c.y; o.v[3] = c.z; o.v[4] = c.w;
    o.v[0] = (w4 > 0) ? p[-1] : c.x;
    o.v[5] = (w4 + 4 < WW) ? p[4] : c.w;
    return o;
}

__global__ __launch_bounds__(128)
void k_sobel_part(const float* __restrict__ x)
{
    int strip = blockIdx.x;
    int b = blockIdx.y, g = blockIdx.z;
    int tid = threadIdx.x;
    int w4 = (tid & 31) * 4;
    int hb = strip * 16 + (tid >> 5) * 4;

    float as[4][4], ms[4][4];
    #pragma unroll
    for (int i = 0; i < 4; i++)
        #pragma unroll
        for (int j = 0; j < 4; j++) { as[i][j] = 0.f; ms[i][j] = 0.f; }

    int c0 = g * CPG;
    for (int c = c0; c < c0 + CPG; c++) {
        const float* plane = x + ((long)(b * CH + c)) * NPIX;
        float* xrp = g_xr + ((long)(b * CH + c)) * NPIX;
        R6v top = load_row_rep(plane, hb - 1, w4);
        R6v mid = load_row_rep(plane, hb,     w4);
        #pragma unroll
        for (int i = 0; i < 4; i++) {
            R6v bot = load_row_rep(plane, hb + 1 + i, w4);
            #pragma unroll
            for (int j = 0; j < 4; j++) {
                float tl = top.v[j], tm = top.v[j+1], tr = top.v[j+2];
                float ml = mid.v[j],                  mr = mid.v[j+2];
                float bl = bot.v[j], bm = bot.v[j+1], br = bot.v[j+2];
                float dx = ((tr - tl) + 2.f * (mr - ml) + (br - bl)) * 0.125f;
                float dy = ((bl - tl) + 2.f * (bm - tm) + (br - tr)) * 0.125f;
                ms[i][j] += fsqrt_fast(dx * dx + dy * dy + 1e-6f);
                as[i][j] += fatan2_fast(dy, dx + 1e-6f);
            }
            // fused: write tf32-rounded x (row hb+i is this iteration's mid row)
            *(float4*)&xrp[(hb + i) * WW + w4] =
                make_float4(f2tf_f(mid.v[1]), f2tf_f(mid.v[2]),
                            f2tf_f(mid.v[3]), f2tf_f(mid.v[4]));
            top = mid; mid = bot;
        }
    }

    float* ap = g_sobp + (long)((b * CGRP + g) * 2 + 0) * NPIX;
    float* mp = g_sobp + (long)((b * CGRP + g) * 2 + 1) * NPIX;
    #pragma unroll
    for (int i = 0; i < 4; i++) {
        int n = (hb + i) * WW + w4;
        *(float4*)&ap[n] = make_float4(as[i][0], as[i][1], as[i][2], as[i][3]);
        *(float4*)&mp[n] = make_float4(ms[i][0], ms[i][1], ms[i][2], ms[i][3]);
    }
}

__global__ void k_hogbin()
{
    int h = blockIdx.x, b = blockIdx.y, w = threadIdx.x;
    int n = h * WW + w;

    float a = 0.f, m = 0.f;
    #pragma unroll
    for (int g = 0; g < CGRP; g++) {
        a += g_sobp[((long)(b * CGRP + g) * 2 + 0) * NPIX + n];
        m += g_sobp[((long)(b * CGRP + g) * 2 + 1) * NPIX + n];
    }
    float mag = m * (1.f / (float)CH);
    float am  = a * (1.f / (float)CH);
    float ang = fmodf(am, PI_F);
    if (ang < 0.f) ang += PI_F;

    const float bw = PI_F / (float)ORI;
    const float ibw = (float)ORI / PI_F;
    #pragma unroll
    for (int o = 0; o < ORI; o++) {
        float ctr = ((float)o + 0.5f) * bw;
        float wt = fmaxf(1.f - fabsf(ang - ctr) * ibw, 0.f);
        g_hog9[(b * ORI + o) * NPIX + n] = wt * mag;
    }
}

// ---------------- TF32 mma GEMM (R10 best config): BM=192, BN=128, 3-stage cp.async ----
#define GBM 192
#define GBN 128
#define GBK 16
#define SAW 20
#define SB  136
#define STG 3
#define A_STG_B (GBM * SAW * 4)   // 15360
#define B_STG_B (GBK * SB * 4)    // 8704
#define GEMM_SMEM (STG * (A_STG_B + B_STG_B))   // 72192

__global__ __launch_bounds__(256, 1)
void k_gemm_tf32(const float* __restrict__ A, const float* __restrict__ B,
                 float* __restrict__ C, int M, int K, int N,
                 long aStr, long bStr, long cStr)
{
    extern __shared__ char dsm[];

    const float* Ab = A + (long)blockIdx.z * aStr;
    const float* Bb = B + (long)blockIdx.z * bStr;
    float*       Cb = C + (long)blockIdx.z * cStr;

    int m0 = blockIdx.y * GBM;
    int n0 = blockIdx.x * GBN;
    int tid = threadIdx.x, lane = tid & 31, warp = tid >> 5;
    int wm = warp & 3, wn = warp >> 2;   // 4 x 2 warps, each 48 x 64
    int fr = lane >> 2, fc = lane & 3;

    uint32_t smemBase = smem_u32(dsm);
    uint32_t aS[STG], bS[STG];
    #pragma unroll
    for (int s = 0; s < STG; s++) {
        aS[s] = smemBase + s * A_STG_B;
        bS[s] = smemBase + STG * A_STG_B + s * B_STG_B;
    }

    uint32_t aRowByte = (uint32_t)(((wm * 48 + (lane & 15)) * SAW + (lane >> 4) * 4) * 4);

    int a_row[3], a_kg[3];
    #pragma unroll
    for (int i = 0; i < 3; i++) { int id = tid + i * 256; a_row[i] = id >> 2; a_kg[i] = id & 3; }
    int b_k[2], b_ng[2];
    #pragma unroll
    for (int i = 0; i < 2; i++) { int id = tid + i * 256; b_k[i] = id >> 5; b_ng[i] = id & 31; }

    #define FILL_STAGE(s, k0) do { \
        _Pragma("unroll") \
        for (int i = 0; i < 3; i++) \
            cp16(aS[s] + (uint32_t)((a_row[i] * SAW + a_kg[i] * 4) * 4), \
                 Ab + (long)(m0 + a_row[i]) * K + (k0) + a_kg[i] * 4); \
        _Pragma("unroll") \
        for (int i = 0; i < 2; i++) \
            cp16(bS[s] + (uint32_t)((b_k[i] * SB + b_ng[i] * 4) * 4), \
                 Bb + (long)((k0) + b_k[i]) * N + n0 + b_ng[i] * 4); \
    } while (0)

    FILL_STAGE(0, 0); CP_COMMIT();
    FILL_STAGE(1, GBK); CP_COMMIT();

    float acc[3][8][4];
    #pragma unroll
    for (int mt = 0; mt < 3; mt++)
        #pragma unroll
        for (int nt = 0; nt < 8; nt++)
            #pragma unroll
            for (int j = 0; j < 4; j++) acc[mt][nt][j] = 0.f;

    int niter = K / GBK;
    for (int it = 0; it < niter; it++) {
        CP_WAIT1();
        __syncthreads();

        int s = it % STG;
        const float* Bp = (const float*)(dsm + STG * A_STG_B + s * B_STG_B);

        #pragma unroll
        for (int ks = 0; ks < 2; ks++) {
            uint32_t af[3][4], bf[8][2];
            #pragma unroll
            for (int mt = 0; mt < 3; mt++)
                ldsm_x4(af[mt][0], af[mt][1], af[mt][2], af[mt][3],
                        aS[s] + aRowByte + (uint32_t)((mt * 16 * SAW + ks * 8) * 4));
            #pragma unroll
            for (int nt = 0; nt < 8; nt++) {
                int n = wn * 64 + nt * 8 + fr;
                bf[nt][0] = __float_as_uint(Bp[(ks * 8 + fc) * SB + n]);
                bf[nt][1] = __float_as_uint(Bp[(ks * 8 + fc + 4) * SB + n]);
            }
            #pragma unroll
            for (int mt = 0; mt < 3; mt++)
                #pragma unroll
                for (int nt = 0; nt < 8; nt++)
                    mma_tf32(acc[mt][nt][0], acc[mt][nt][1], acc[mt][nt][2], acc[mt][nt][3],
                             af[mt][0], af[mt][1], af[mt][2], af[mt][3],
                             bf[nt][0], bf[nt][1]);
        }

        if (it + 2 < niter) FILL_STAGE((it + 2) % STG, (it + 2) * GBK);
        CP_COMMIT();   // empty group when no fill: keeps wait_group(1) invariant
    }

    #pragma unroll
    for (int mt = 0; mt < 3; mt++) {
        #pragma unroll
        for (int nt = 0; nt < 8; nt++) {
            int gm = m0 + wm * 48 + mt * 16 + fr;
            int gn = n0 + wn * 64 + nt * 8 + fc * 2;
            float2 lo = make_float2(acc[mt][nt][0], acc[mt][nt][1]);
            float2 hi = make_float2(acc[mt][nt][2], acc[mt][nt][3]);
            *(float2*)&Cb[(long)gm * N + gn] = lo;
            *(float2*)&Cb[(long)(gm + 8) * N + gn] = hi;
        }
    }
    #undef FILL_STAGE
}

// ---------------- depthwise 3x3 + HOG add + norm partials ----------------
__global__ __launch_bounds__(128)
void k_dwconv(const float* __restrict__ wdw, const float* __restrict__ whog)
{
    int strip = blockIdx.x;
    int ch = blockIdx.y, b = blockIdx.z;
    int tid = threadIdx.x;
    int w4 = (tid & 31) * 4;
    int hb = strip * 32 + (tid >> 5) * 8;

    const float* plane = g_qkv + ((long)(b * C3 + ch)) * NPIX;
    const float* kwp = wdw + ch * 9;
    float k00 = kwp[0], k01 = kwp[1], k02 = kwp[2];
    float k10 = kwp[3], k11 = kwp[4], k12 = kwp[5];
    float k20 = kwp[6], k21 = kwp[7], k22 = kwp[8];

    bool isv = (ch >= 2 * CH);
    float wh[ORI];
    if (isv) {
        int d = ch - 2 * CH;
        #pragma unroll
        for (int o = 0; o < ORI; o++) wh[o] = whog[d * ORI + o];
    }

    float* outp = g_qkvd + ((long)(b * C3 + ch)) * NPIX;
    const float* hogp = g_hog9 + (long)b * ORI * NPIX;

    R6v top = load_row_zero(plane, hb - 1, w4);
    R6v mid = load_row_zero(plane, hb,     w4);
    float ssq = 0.f;

    #pragma unroll
    for (int i = 0; i < 8; i++) {
        R6v bot = load_row_zero(plane, hb + 1 + i, w4);
        float o0, o1, o2, o3;
        o0 = top.v[0]*k00 + top.v[1]*k01 + top.v[2]*k02
           + mid.v[0]*k10 + mid.v[1]*k11 + mid.v[2]*k12
           + bot.v[0]*k20 + bot.v[1]*k21 + bot.v[2]*k22;
        o1 = top.v[1]*k00 + top.v[2]*k01 + top.v[3]*k02
           + mid.v[1]*k10 + mid.v[2]*k11 + mid.v[3]*k12
           + bot.v[1]*k20 + bot.v[2]*k21 + bot.v[3]*k22;
        o2 = top.v[2]*k00 + top.v[3]*k01 + top.v[4]*k02
           + mid.v[2]*k10 + mid.v[3]*k11 + mid.v[4]*k12
           + bot.v[2]*k20 + bot.v[3]*k21 + bot.v[4]*k22;
        o3 = top.v[3]*k00 + top.v[4]*k01 + top.v[5]*k02
           + mid.v[3]*k10 + mid.v[4]*k11 + mid.v[5]*k12
           + bot.v[3]*k20 + bot.v[4]*k21 + bot.v[5]*k22;

        int n = (hb + i) * WW + w4;
        if (isv) {
            #pragma unroll
            for (int o = 0; o < ORI; o++) {
                float4 h = *(const float4*)&hogp[(long)o * NPIX + n];
                o0 += wh[o] * h.x; o1 += wh[o] * h.y;
                o2 += wh[o] * h.z; o3 += wh[o] * h.w;
            }
            o0 = f2tf_f(o0); o1 = f2tf_f(o1); o2 = f2tf_f(o2); o3 = f2tf_f(o3);
        } else {
            ssq += o0*o0 + o1*o1 + o2*o2 + o3*o3;
        }
        *(float4*)&outp[n] = make_float4(o0, o1, o2, o3);
        top = mid; mid = bot;
    }

    if (!isv) {
        int lane = tid & 31, warp = tid >> 5;
        #pragma unroll
        for (int off = 16; off; off >>= 1) ssq += __shfl_xor_sync(0xffffffffu, ssq, off);
        __shared__ float red[4];
        if (lane == 0) red[warp] = ssq;
        __syncthreads();
        if (tid == 0)
            g_npart[(b * 2 * CH + ch) * 4 + strip] = red[0] + red[1] + red[2] + red[3];
    }
}

__global__ void k_norm2()
{
    int r = blockIdx.x, b = blockIdx.y, t = threadIdx.x;
    float v = (t < 4) ? g_npart[(b * 2 * CH + r) * 4 + t] : 0.f;
    #pragma unroll
    for (int off = 16; off; off >>= 1) v += __shfl_xor_sync(0xffffffffu, v, off);
    if (t == 0) g_norms[b * 2 * CH + r] = fmaxf(sqrtf(v), 1e-12f);
}

// ---------------- S partial = q . k^T (float2-vectorized, order-preserving) ------------
__global__ __launch_bounds__(256)
void k_spart()
{
    int sp = blockIdx.x, hh = blockIdx.y, b = blockIdx.z;
    int tid = threadIdx.x;
    __shared__ float qs[HDIM][66];   // even stride: float2 loads 8B-aligned
    __shared__ float ks[HDIM][66];

    const float* qp = g_qkvd + ((long)(b * C3 + hh * HDIM)) * NPIX;
    const float* kp = g_qkvd + ((long)(b * C3 + CH + hh * HDIM)) * NPIX;

    int c0 = (tid >> 4) * 3;
    int d0 = (tid & 15) * 3;
    float acc[3][3];
    #pragma unroll
    for (int i = 0; i < 3; i++)
        #pragma unroll
        for (int j = 0; j < 3; j++) acc[i][j] = 0.f;

    int nbase = sp * (NPIX / NSPLIT);
    for (int chunk = 0; chunk < 8; chunk++) {
        int n0 = nbase + chunk * 64;
        __syncthreads();
        #pragma unroll
        for (int l = 0; l < 12; l++) {
            int e = l * 256 + tid;
            int c = e >> 6, nn = e & 63;
            qs[c][nn] = qp[(long)c * NPIX + n0 + nn];
            ks[c][nn] = kp[(long)c * NPIX + n0 + nn];
        }
        __syncthreads();
        #pragma unroll 8
        for (int m = 0; m < 32; m++) {
            float2 a0 = *(float2*)&qs[c0][2*m];
            float2 a1 = *(float2*)&qs[c0 + 1][2*m];
            float2 a2 = *(float2*)&qs[c0 + 2][2*m];
            float2 b0 = *(float2*)&ks[d0][2*m];
            float2 b1 = *(float2*)&ks[d0 + 1][2*m];
            float2 b2 = *(float2*)&ks[d0 + 2][2*m];
            // nn = 2m then nn = 2m+1 — same accumulation order as scalar version
            acc[0][0] += a0.x * b0.x; acc[0][0] += a0.y * b0.y;
            acc[0][1] += a0.x * b1.x; acc[0][1] += a0.y * b1.y;
            acc[0][2] += a0.x * b2.x; acc[0][2] += a0.y * b2.y;
            acc[1][0] += a1.x * b0.x; acc[1][0] += a1.y * b0.y;
            acc[1][1] += a1.x * b1.x; acc[1][1] += a1.y * b1.y;
            acc[1][2] += a1.x * b2.x; acc[1][2] += a1.y * b2.y;
            acc[2][0] += a2.x * b0.x; acc[2][0] += a2.y * b0.y;
            acc[2][1] += a2.x * b1.x; acc[2][1] += a2.y * b1.y;
            acc[2][2] += a2.x * b2.x; acc[2][2] += a2.y * b2.y;
        }
    }

    float* op = g_spart + (((long)(b * NHEAD + hh) * NSPLIT + sp) * HDIM) * HDIM;
    #pragma unroll
    for (int i = 0; i < 3; i++)
        #pragma unroll
        for (int j = 0; j < 3; j++)
            op[(c0 + i) * HDIM + d0 + j] = acc[i][j];
}

__global__ void k_softmax(const float* __restrict__ temp)
{
    int hh = blockIdx.x, b = blockIdx.y, tid = threadIdx.x;
    __shared__ float sS[HDIM][HDIM];
    float tv = temp[hh];

    const float* base = g_spart + (long)(b * NHEAD + hh) * NSPLIT * HDIM * HDIM;
    for (int e = tid; e < HDIM * HDIM; e += 256) {
        float s = 0.f;
        for (int sp = 0; sp < NSPLIT; sp++) s += base[sp * HDIM * HDIM + e];
        int c = e / HDIM, d = e % HDIM;
        float nq = g_norms[b * 2 * CH + hh * HDIM + c];
        float nk = g_norms[b * 2 * CH + CH + hh * HDIM + d];
        sS[c][d] = s * tv / (nq * nk);
    }
    __syncthreads();

    int warp = tid >> 5, lane = tid & 31;
    for (int r = warp; r < HDIM; r += 8) {
        float v0 = sS[r][lane];
        float v1 = (lane + 32 < HDIM) ? sS[r][lane + 32] : -3.4e38f;
        float m = fmaxf(v0, v1);
        #pragma unroll
        for (int off = 16; off; off >>= 1) m = fmaxf(m, __shfl_xor_sync(0xffffffffu, m, off));
        float e0 = expf(v0 - m);
        float e1 = (lane + 32 < HDIM) ? expf(v1 - m) : 0.f;
        float s = e0 + e1;
        #pragma unroll
        for (int off = 16; off; off >>= 1) s += __shfl_xor_sync(0xffffffffu, s, off);
        float inv = 1.f / s;
        float* op = g_attn + ((long)(b * NHEAD + hh) * HDIM + r) * HDIM;
        op[lane] = e0 * inv;
        if (lane + 32 < HDIM) op[lane + 32] = e1 * inv;
    }
}

// Mb rounded to tf32 values at write (GEMM2 A operand)
__global__ void k_mb(const float* __restrict__ wproj)
{
    int d = blockIdx.x, b = blockIdx.y, e = threadIdx.x;
    int hh = d / HDIM, dl = d % HDIM;
    __shared__ float acol[HDIM];
    if (e < HDIM) acol[e] = g_attn[((long)(b * NHEAD + hh) * HDIM + e) * HDIM + dl];
    __syncthreads();
    const float* wp = wproj + e * CH + hh * HDIM;
    float s = 0.f;
    #pragma unroll
    for (int c = 0; c < HDIM; c++) s += wp[c] * acol[c];
    g_mb[((long)(b * CH + e)) * CH + d] = f2tf_f(s);
}

// ---------------- launch ----------------
extern "C" void kernel_launch(void* const* d_in, const int* in_sizes, int n_in,
                              void* d_out, int out_size)
{
    const float* x     = (const float*)d_in[0];
    const float* Wqkv  = (const float*)d_in[1];
    const float* Wdw   = (const float*)d_in[2];
    const float* Whog  = (const float*)d_in[3];
    const float* Wproj = (const float*)d_in[4];
    const float* temp  = (const float*)d_in[5];
    float* out = (float*)d_out;

    float *p_qkv, *p_qkvd, *p_mb, *p_xr, *p_wr;
    cudaGetSymbolAddress((void**)&p_qkv,  g_qkv);
    cudaGetSymbolAddress((void**)&p_qkvd, g_qkvd);
    cudaGetSymbolAddress((void**)&p_mb,   g_mb);
    cudaGetSymbolAddress((void**)&p_xr,   g_xr);
    cudaGetSymbolAddress((void**)&p_wr,   g_wr);

    cudaFuncSetAttribute(k_gemm_tf32, cudaFuncAttributeMaxDynamicSharedMemorySize, GEMM_SMEM);

    // launches 0-2 (GEMM1 stays at capture index 3)
    k_sobel_part<<<dim3(8, BATCH, CGRP), 128>>>(x);   // also writes g_xr (rounded x)
    k_round<<<(C3 * CH) / 4 / 256, 256>>>((const float4*)Wqkv, (float4*)p_wr);
    k_hogbin<<<dim3(HH, BATCH), WW>>>();

    // launch 3: QKV 1x1 conv (tf32 mma, 3-stage cp.async — R10 best config)
    k_gemm_tf32<<<dim3(NPIX / GBN, C3 / GBM, BATCH), 256, GEMM_SMEM>>>(
        p_wr, p_xr, p_qkv, C3, CH, NPIX,
        0L, (long)CH * NPIX, (long)C3 * NPIX);

    // depthwise 3x3 + HOG add + norm partials (v rounded at write)
    k_dwconv<<<dim3(4, C3, BATCH), 128>>>(Wdw, Whog);

    // finalize q/k norms
    k_norm2<<<dim3(2 * CH, BATCH), 32>>>();

    // S partials
    k_spart<<<dim3(NSPLIT, NHEAD, BATCH), 256>>>();

    // softmax
    k_softmax<<<dim3(NHEAD, BATCH), 256>>>(temp);

    // Mb = W_proj @ blockdiag(attn)  (rounded at write)
    k_mb<<<dim3(CH, BATCH), CH>>>(Wproj);

    // out = Mb @ v (tf32 mma)
    k_gemm_tf32<<<dim3(NPIX / GBN, CH / GBM, BATCH), 256, GEMM_SMEM>>>(
        p_mb, p_qkvd + (long)2 * CH * NPIX, out, CH, CH, NPIX,
        (long)CH * CH, (long)C3 * NPIX, (long)CH * NPIX);
}

// round 15
// speedup vs baseline: 1.2021x; 1.0272x over previous
#include <cuda_runtime.h>
#include <math.h>
#include <stdint.h>

#define BATCH 8
#define CH    192
#define C3    576
#define HH    128
#define WW    128
#define NPIX  16384
#define ORI   9
#define NHEAD 4
#define HDIM  48
#define NSPLIT 32
#define CGRP  16
#define CPG   (CH / CGRP)

#define PI_F 3.14159265358979323846f

// ---------------- scratch ----------------
__device__ float g_qkv [BATCH * C3 * NPIX];
__device__ float g_qkvd[BATCH * C3 * NPIX];
__device__ float g_xr  [BATCH * CH * NPIX];      // x pre-rounded to tf32 (written by sobel)
__device__ float g_wr  [C3 * CH];                // Wqkv pre-rounded
__device__ float g_hog9[BATCH * ORI * NPIX];
__device__ float g_sobp[BATCH * CGRP * 2 * NPIX];
__device__ float g_norms[BATCH * 2 * CH];
__device__ float g_npart[BATCH * 2 * CH * 4];
__device__ float g_spart[BATCH * NHEAD * NSPLIT * HDIM * HDIM];
__device__ float g_attn [BATCH * NHEAD * HDIM * HDIM];
__device__ float g_mb   [BATCH * CH * CH];

// ---------------- fast math (MUFU-free) ----------------
__device__ __forceinline__ float frcp_fast(float x) {
    float r = __uint_as_float(0x7EF311C3u - __float_as_uint(x));
    r = r * (2.f - x * r);
    r = r * (2.f - x * r);
    r = r * (2.f - x * r);
    return r;
}
__device__ __forceinline__ float fsqrt_fast(float x) {
    float r = __uint_as_float(0x5F3759DFu - (__float_as_uint(x) >> 1));
    r = r * (1.5f - 0.5f * x * r * r);
    r = r * (1.5f - 0.5f * x * r * r);
    return x * r;
}
__device__ __forceinline__ float fatan2_fast(float y, float x) {
    float ax = fabsf(x), ay = fabsf(y);
    float mx = fmaxf(ax, ay), mn = fminf(ax, ay);
    float t = mn * frcp_fast(fmaxf(mx, 1e-37f));
    float s = t * t;
    float p = -0.0117212f;
    p = fmaf(p, s,  0.05265332f);
    p = fmaf(p, s, -0.11643287f);
    p = fmaf(p, s,  0.19354346f);
    p = fmaf(p, s, -0.33262347f);
    p = fmaf(p, s,  0.99997726f);
    float a = t * p;
    a = (ay > ax) ? (1.57079632679f - a) : a;
    a = (x < 0.f) ? (3.14159265359f - a) : a;
    return copysignf(a, y);
}

// ---------------- tf32 / mma helpers ----------------
__device__ __forceinline__ float f2tf_f(float x) {
    uint32_t r; asm("cvt.rna.tf32.f32 %0, %1;" : "=r"(r) : "f"(x));
    return __uint_as_float(r);
}
__device__ __forceinline__ void mma_tf32(float& c0, float& c1, float& c2, float& c3,
                                         uint32_t a0, uint32_t a1, uint32_t a2, uint32_t a3,
                                         uint32_t b0, uint32_t b1) {
    asm volatile("mma.sync.aligned.m16n8k8.row.col.f32.tf32.tf32.f32 "
                 "{%0,%1,%2,%3}, {%4,%5,%6,%7}, {%8,%9}, {%0,%1,%2,%3};"
                 : "+f"(c0), "+f"(c1), "+f"(c2), "+f"(c3)
                 : "r"(a0), "r"(a1), "r"(a2), "r"(a3), "r"(b0), "r"(b1));
}
__device__ __forceinline__ void ldsm_x4(uint32_t& r0, uint32_t& r1, uint32_t& r2, uint32_t& r3,
                                        uint32_t addr) {
    asm volatile("ldmatrix.sync.aligned.m8n8.x4.shared.b16 {%0,%1,%2,%3}, [%4];"
                 : "=r"(r0), "=r"(r1), "=r"(r2), "=r"(r3) : "r"(addr));
}
__device__ __forceinline__ uint32_t smem_u32(const void* p) {
    uint32_t a;
    asm("{ .reg .u64 t; cvta.to.shared.u64 t, %1; cvt.u32.u64 %0, t; }" : "=r"(a) : "l"(p));
    return a;
}
__device__ __forceinline__ void cp16(uint32_t s, const float* g) {
    asm volatile("cp.async.cg.shared.global [%0], [%1], 16;" :: "r"(s), "l"(g));
}
#define CP_COMMIT() asm volatile("cp.async.commit_group;" ::: "memory")
#define CP_WAIT1()  asm volatile("cp.async.wait_group 1;" ::: "memory")

// ---------------- elementwise tf32 pre-round (weights only) ----------------
__global__ __launch_bounds__(256)
void k_round(const float4* __restrict__ src, float4* __restrict__ dst)
{
    long i = (long)blockIdx.x * 256 + threadIdx.x;
    float4 v = src[i];
    dst[i] = make_float4(f2tf_f(v.x), f2tf_f(v.y), f2tf_f(v.z), f2tf_f(v.w));
}

// ---------------- Sobel (+ fused tf32 rounding of x into g_xr) ----------------
struct R6v { float v[6]; };
__device__ __forceinline__ R6v load_row_zero(const float* plane, int r, int w4) {
    R6v o;
    if (r < 0 || r >= HH) {
        #pragma unroll
        for (int i = 0; i < 6; i++) o.v[i] = 0.f;
        return o;
    }
    const float* p = plane + r * WW + w4;
    float4 c = *(const float4*)p;
    o.v[0] = (w4 > 0) ? p[-1] : 0.f;
    o.v[1] = c.x; o.v[2] = c.y; o.v[3] = c.z; o.v[4] = c.w;
    o.v[5] = (w4 + 4 < WW) ? p[4] : 0.f;
    return o;
}
__device__ __forceinline__ R6v load_row_rep(const float* plane, int r, int w4) {
    int rc = min(max(r, 0), HH - 1);
    const float* p = plane + rc * WW + w4;
    float4 c = *(const float4*)p;
    R6v o;
    o.v[1] = c.x; o.v[2] = c.y; o.v[3] = c.z; o.v[4] = c.w;
    o.v[0] = (w4 > 0) ? p[-1] : c.x;
    o.v[5] = (w4 + 4 < WW) ? p[4] : c.w;
    return o;
}

__global__ __launch_bounds__(128)
void k_sobel_part(const float* __restrict__ x)
{
    int strip = blockIdx.x;
    int b = blockIdx.y, g = blockIdx.z;
    int tid = threadIdx.x;
    int w4 = (tid & 31) * 4;
    int hb = strip * 16 + (tid >> 5) * 4;

    float as[4][4], ms[4][4];
    #pragma unroll
    for (int i = 0; i < 4; i++)
        #pragma unroll
        for (int j = 0; j < 4; j++) { as[i][j] = 0.f; ms[i][j] = 0.f; }

    int c0 = g * CPG;
    for (int c = c0; c < c0 + CPG; c++) {
        const float* plane = x + ((long)(b * CH + c)) * NPIX;
        float* xrp = g_xr + ((long)(b * CH + c)) * NPIX;
        R6v top = load_row_rep(plane, hb - 1, w4);
        R6v mid = load_row_rep(plane, hb,     w4);
        #pragma unroll
        for (int i = 0; i < 4; i++) {
            R6v bot = load_row_rep(plane, hb + 1 + i, w4);
            #pragma unroll
            for (int j = 0; j < 4; j++) {
                float tl = top.v[j], tm = top.v[j+1], tr = top.v[j+2];
                float ml = mid.v[j],                  mr = mid.v[j+2];
                float bl = bot.v[j], bm = bot.v[j+1], br = bot.v[j+2];
                float dx = ((tr - tl) + 2.f * (mr - ml) + (br - bl)) * 0.125f;
                float dy = ((bl - tl) + 2.f * (bm - tm) + (br - tr)) * 0.125f;
                ms[i][j] += fsqrt_fast(dx * dx + dy * dy + 1e-6f);
                as[i][j] += fatan2_fast(dy, dx + 1e-6f);
            }
            // fused: write tf32-rounded x (row hb+i is this iteration's mid row)
            *(float4*)&xrp[(hb + i) * WW + w4] =
                make_float4(f2tf_f(mid.v[1]), f2tf_f(mid.v[2]),
                            f2tf_f(mid.v[3]), f2tf_f(mid.v[4]));
            top = mid; mid = bot;
        }
    }

    float* ap = g_sobp + (long)((b * CGRP + g) * 2 + 0) * NPIX;
    float* mp = g_sobp + (long)((b * CGRP + g) * 2 + 1) * NPIX;
    #pragma unroll
    for (int i = 0; i < 4; i++) {
        int n = (hb + i) * WW + w4;
        *(float4*)&ap[n] = make_float4(as[i][0], as[i][1], as[i][2], as[i][3]);
        *(float4*)&mp[n] = make_float4(ms[i][0], ms[i][1], ms[i][2], ms[i][3]);
    }
}

__global__ void k_hogbin()
{
    int h = blockIdx.x, b = blockIdx.y, w = threadIdx.x;
    int n = h * WW + w;

    float a = 0.f, m = 0.f;
    #pragma unroll
    for (int g = 0; g < CGRP; g++) {
        a += g_sobp[((long)(b * CGRP + g) * 2 + 0) * NPIX + n];
        m += g_sobp[((long)(b * CGRP + g) * 2 + 1) * NPIX + n];
    }
    float mag = m * (1.f / (float)CH);
    float am  = a * (1.f / (float)CH);
    float ang = fmodf(am, PI_F);
    if (ang < 0.f) ang += PI_F;

    const float bw = PI_F / (float)ORI;
    const float ibw = (float)ORI / PI_F;
    #pragma unroll
    for (int o = 0; o < ORI; o++) {
        float ctr = ((float)o + 0.5f) * bw;
        float wt = fmaxf(1.f - fabsf(ang - ctr) * ibw, 0.f);
        g_hog9[(b * ORI + o) * NPIX + n] = wt * mag;
    }
}

// ---------------- TF32 mma GEMM: BM=192, BN=128, GBK=48, 3-stage cp.async ----------
// Operands PRE-ROUNDED to tf32 values; kernel copies raw bytes. K fixed = 192.
#define GBM 192
#define GBN 128
#define GBK 48
#define SAW 52    // A row stride (words): 208 B (16B-aligned), LDSM 8-row phases conflict-free
#define SB  136
#define STG 3
#define A_STG_B (GBM * SAW * 4)   // 39936
#define B_STG_B (GBK * SB * 4)    // 26112
#define GEMM_SMEM (STG * (A_STG_B + B_STG_B))   // 198144

__global__ __launch_bounds__(256, 1)
void k_gemm_tf32(const float* __restrict__ A, const float* __restrict__ B,
                 float* __restrict__ C, int M, int K, int N,
                 long aStr, long bStr, long cStr)
{
    extern __shared__ char dsm[];

    const float* Ab = A + (long)blockIdx.z * aStr;
    const float* Bb = B + (long)blockIdx.z * bStr;
    float*       Cb = C + (long)blockIdx.z * cStr;

    int m0 = blockIdx.y * GBM;
    int n0 = blockIdx.x * GBN;
    int tid = threadIdx.x, lane = tid & 31, warp = tid >> 5;
    int wm = warp & 3, wn = warp >> 2;   // 4 x 2 warps, each 48 x 64
    int fr = lane >> 2, fc = lane & 3;

    uint32_t smemBase = smem_u32(dsm);
    uint32_t aS[STG], bS[STG];
    #pragma unroll
    for (int s = 0; s < STG; s++) {
        aS[s] = smemBase + s * A_STG_B;
        bS[s] = smemBase + STG * A_STG_B + s * B_STG_B;
    }

    uint32_t aRowByte = (uint32_t)(((wm * 48 + (lane & 15)) * SAW + (lane >> 4) * 4) * 4);

    // A fill: 192 rows x 48 k = 2304 float4, 9 per thread
    int a_row[9], a_kg[9];
    #pragma unroll
    for (int i = 0; i < 9; i++) { int id = tid + i * 256; a_row[i] = id / 12; a_kg[i] = id % 12; }
    // B fill: 48 k-rows x 128 n = 1536 float4, 6 per thread
    int b_k[6], b_ng[6];
    #pragma unroll
    for (int i = 0; i < 6; i++) { int id = tid + i * 256; b_k[i] = id >> 5; b_ng[i] = id & 31; }

    #define FILL_STAGE(s, k0) do { \
        _Pragma("unroll") \
        for (int i = 0; i < 9; i++) \
            cp16(aS[s] + (uint32_t)((a_row[i] * SAW + a_kg[i] * 4) * 4), \
                 Ab + (long)(m0 + a_row[i]) * K + (k0) + a_kg[i] * 4); \
        _Pragma("unroll") \
        for (int i = 0; i < 6; i++) \
            cp16(bS[s] + (uint32_t)((b_k[i] * SB + b_ng[i] * 4) * 4), \
                 Bb + (long)((k0) + b_k[i]) * N + n0 + b_ng[i] * 4); \
    } while (0)

    FILL_STAGE(0, 0); CP_COMMIT();
    FILL_STAGE(1, GBK); CP_COMMIT();

    float acc[3][8][4];
    #pragma unroll
    for (int mt = 0; mt < 3; mt++)
        #pragma unroll
        for (int nt = 0; nt < 8; nt++)
            #pragma unroll
            for (int j = 0; j < 4; j++) acc[mt][nt][j] = 0.f;

    int niter = K / GBK;   // 4
    for (int it = 0; it < niter; it++) {
        CP_WAIT1();
        __syncthreads();

        int s = it % STG;
        const float* Bp = (const float*)(dsm + STG * A_STG_B + s * B_STG_B);

        #pragma unroll
        for (int ks = 0; ks < 6; ks++) {
            uint32_t af[3][4], bf[8][2];
            #pragma unroll
            for (int mt = 0; mt < 3; mt++)
                ldsm_x4(af[mt][0], af[mt][1], af[mt][2], af[mt][3],
                        aS[s] + aRowByte + (uint32_t)((mt * 16 * SAW + ks * 8) * 4));
            #pragma unroll
            for (int nt = 0; nt < 8; nt++) {
                int n = wn * 64 + nt * 8 + fr;
                bf[nt][0] = __float_as_uint(Bp[(ks * 8 + fc) * SB + n]);
                bf[nt][1] = __float_as_uint(Bp[(ks * 8 + fc + 4) * SB + n]);
            }
            #pragma unroll
            for (int mt = 0; mt < 3; mt++)
                #pragma unroll
                for (int nt = 0; nt < 8; nt++)
                    mma_tf32(acc[mt][nt][0], acc[mt][nt][1], acc[mt][nt][2], acc[mt][nt][3],
                             af[mt][0], af[mt][1], af[mt][2], af[mt][3],
                             bf[nt][0], bf[nt][1]);
        }

        if (it + 2 < niter) FILL_STAGE((it + 2) % STG, (it + 2) * GBK);
        CP_COMMIT();   // empty group when no fill: keeps wait_group(1) invariant
    }

    #pragma unroll
    for (int mt = 0; mt < 3; mt++) {
        #pragma unroll
        for (int nt = 0; nt < 8; nt++) {
            int gm = m0 + wm * 48 + mt * 16 + fr;
            int gn = n0 + wn * 64 + nt * 8 + fc * 2;
            float2 lo = make_float2(acc[mt][nt][0], acc[mt][nt][1]);
            float2 hi = make_float2(acc[mt][nt][2], acc[mt][nt][3]);
            *(float2*)&Cb[(long)gm * N + gn] = lo;
            *(float2*)&Cb[(long)(gm + 8) * N + gn] = hi;
        }
    }
    #undef FILL_STAGE
}

// ---------------- depthwise 3x3 + HOG add + norm partials ----------------
__global__ __launch_bounds__(128)
void k_dwconv(const float* __restrict__ wdw, const float* __restrict__ whog)
{
    int strip = blockIdx.x;
    int ch = blockIdx.y, b = blockIdx.z;
    int tid = threadIdx.x;
    int w4 = (tid & 31) * 4;
    int hb = strip * 32 + (tid >> 5) * 8;

    const float* plane = g_qkv + ((long)(b * C3 + ch)) * NPIX;
    const float* kwp = wdw + ch * 9;
    float k00 = kwp[0], k01 = kwp[1], k02 = kwp[2];
    float k10 = kwp[3], k11 = kwp[4], k12 = kwp[5];
    float k20 = kwp[6], k21 = kwp[7], k22 = kwp[8];

    bool isv = (ch >= 2 * CH);
    float wh[ORI];
    if (isv) {
        int d = ch - 2 * CH;
        #pragma unroll
        for (int o = 0; o < ORI; o++) wh[o] = whog[d * ORI + o];
    }

    float* outp = g_qkvd + ((long)(b * C3 + ch)) * NPIX;
    const float* hogp = g_hog9 + (long)b * ORI * NPIX;

    R6v top = load_row_zero(plane, hb - 1, w4);
    R6v mid = load_row_zero(plane, hb,     w4);
    float ssq = 0.f;

    #pragma unroll
    for (int i = 0; i < 8; i++) {
        R6v bot = load_row_zero(plane, hb + 1 + i, w4);
        float o0, o1, o2, o3;
        o0 = top.v[0]*k00 + top.v[1]*k01 + top.v[2]*k02
           + mid.v[0]*k10 + mid.v[1]*k11 + mid.v[2]*k12
           + bot.v[0]*k20 + bot.v[1]*k21 + bot.v[2]*k22;
        o1 = top.v[1]*k00 + top.v[2]*k01 + top.v[3]*k02
           + mid.v[1]*k10 + mid.v[2]*k11 + mid.v[3]*k12
           + bot.v[1]*k20 + bot.v[2]*k21 + bot.v[3]*k22;
        o2 = top.v[2]*k00 + top.v[3]*k01 + top.v[4]*k02
           + mid.v[2]*k10 + mid.v[3]*k11 + mid.v[4]*k12
           + bot.v[2]*k20 + bot.v[3]*k21 + bot.v[4]*k22;
        o3 = top.v[3]*k00 + top.v[4]*k01 + top.v[5]*k02
           + mid.v[3]*k10 + mid.v[4]*k11 + mid.v[5]*k12
           + bot.v[3]*k20 + bot.v[4]*k21 + bot.v[5]*k22;

        int n = (hb + i) * WW + w4;
        if (isv) {
            #pragma unroll
            for (int o = 0; o < ORI; o++) {
                float4 h = *(const float4*)&hogp[(long)o * NPIX + n];
                o0 += wh[o] * h.x; o1 += wh[o] * h.y;
                o2 += wh[o] * h.z; o3 += wh[o] * h.w;
            }
            o0 = f2tf_f(o0); o1 = f2tf_f(o1); o2 = f2tf_f(o2); o3 = f2tf_f(o3);
        } else {
            ssq += o0*o0 + o1*o1 + o2*o2 + o3*o3;
        }
        *(float4*)&outp[n] = make_float4(o0, o1, o2, o3);
        top = mid; mid = bot;
    }

    if (!isv) {
        int lane = tid & 31, warp = tid >> 5;
        #pragma unroll
        for (int off = 16; off; off >>= 1) ssq += __shfl_xor_sync(0xffffffffu, ssq, off);
        __shared__ float red[4];
        if (lane == 0) red[warp] = ssq;
        __syncthreads();
        if (tid == 0)
            g_npart[(b * 2 * CH + ch) * 4 + strip] = red[0] + red[1] + red[2] + red[3];
    }
}

__global__ void k_norm2()
{
    int r = blockIdx.x, b = blockIdx.y, t = threadIdx.x;
    float v = (t < 4) ? g_npart[(b * 2 * CH + r) * 4 + t] : 0.f;
    #pragma unroll
    for (int off = 16; off; off >>= 1) v += __shfl_xor_sync(0xffffffffu, v, off);
    if (t == 0) g_norms[b * 2 * CH + r] = fmaxf(sqrtf(v), 1e-12f);
}

// ---------------- S partial = q . k^T (float2-vectorized, order-preserving) ------------
__global__ __launch_bounds__(256)
void k_spart()
{
    int sp = blockIdx.x, hh = blockIdx.y, b = blockIdx.z;
    int tid = threadIdx.x;
    __shared__ float qs[HDIM][66];
    __shared__ float ks[HDIM][66];

    const float* qp = g_qkvd + ((long)(b * C3 + hh * HDIM)) * NPIX;
    const float* kp = g_qkvd + ((long)(b * C3 + CH + hh * HDIM)) * NPIX;

    int c0 = (tid >> 4) * 3;
    int d0 = (tid & 15) * 3;
    float acc[3][3];
    #pragma unroll
    for (int i = 0; i < 3; i++)
        #pragma unroll
        for (int j = 0; j < 3; j++) acc[i][j] = 0.f;

    int nbase = sp * (NPIX / NSPLIT);
    for (int chunk = 0; chunk < 8; chunk++) {
        int n0 = nbase + chunk * 64;
        __syncthreads();
        #pragma unroll
        for (int l = 0; l < 12; l++) {
            int e = l * 256 + tid;
            int c = e >> 6, nn = e & 63;
            qs[c][nn] = qp[(long)c * NPIX + n0 + nn];
            ks[c][nn] = kp[(long)c * NPIX + n0 + nn];
        }
        __syncthreads();
        #pragma unroll 8
        for (int m = 0; m < 32; m++) {
            float2 a0 = *(float2*)&qs[c0][2*m];
            float2 a1 = *(float2*)&qs[c0 + 1][2*m];
            float2 a2 = *(float2*)&qs[c0 + 2][2*m];
            float2 b0 = *(float2*)&ks[d0][2*m];
            float2 b1 = *(float2*)&ks[d0 + 1][2*m];
            float2 b2 = *(float2*)&ks[d0 + 2][2*m];
            acc[0][0] += a0.x * b0.x; acc[0][0] += a0.y * b0.y;
            acc[0][1] += a0.x * b1.x; acc[0][1] += a0.y * b1.y;
            acc[0][2] += a0.x * b2.x; acc[0][2] += a0.y * b2.y;
            acc[1][0] += a1.x * b0.x; acc[1][0] += a1.y * b0.y;
            acc[1][1] += a1.x * b1.x; acc[1][1] += a1.y * b1.y;
            acc[1][2] += a1.x * b2.x; acc[1][2] += a1.y * b2.y;
            acc[2][0] += a2.x * b0.x; acc[2][0] += a2.y * b0.y;
            acc[2][1] += a2.x * b1.x; acc[2][1] += a2.y * b1.y;
            acc[2][2] += a2.x * b2.x; acc[2][2] += a2.y * b2.y;
        }
    }

    float* op = g_spart + (((long)(b * NHEAD + hh) * NSPLIT + sp) * HDIM) * HDIM;
    #pragma unroll
    for (int i = 0; i < 3; i++)
        #pragma unroll
        for (int j = 0; j < 3; j++)
            op[(c0 + i) * HDIM + d0 + j] = acc[i][j];
}

__global__ void k_softmax(const float* __restrict__ temp)
{
    int hh = blockIdx.x, b = blockIdx.y, tid = threadIdx.x;
    __shared__ float sS[HDIM][HDIM];
    float tv = temp[hh];

    const float* base = g_spart + (long)(b * NHEAD + hh) * NSPLIT * HDIM * HDIM;
    for (int e = tid; e < HDIM * HDIM; e += 256) {
        float s = 0.f;
        for (int sp = 0; sp < NSPLIT; sp++) s += base[sp * HDIM * HDIM + e];
        int c = e / HDIM, d = e % HDIM;
        float nq = g_norms[b * 2 * CH + hh * HDIM + c];
        float nk = g_norms[b * 2 * CH + CH + hh * HDIM + d];
        sS[c][d] = s * tv / (nq * nk);
    }
    __syncthreads();

    int warp = tid >> 5, lane = tid & 31;
    for (int r = warp; r < HDIM; r += 8) {
        float v0 = sS[r][lane];
        float v1 = (lane + 32 < HDIM) ? sS[r][lane + 32] : -3.4e38f;
        float m = fmaxf(v0, v1);
        #pragma unroll
        for (int off = 16; off; off >>= 1) m = fmaxf(m, __shfl_xor_sync(0xffffffffu, m, off));
        float e0 = expf(v0 - m);
        float e1 = (lane + 32 < HDIM) ? expf(v1 - m) : 0.f;
        float s = e0 + e1;
        #pragma unroll
        for (int off = 16; off; off >>= 1) s += __shfl_xor_sync(0xffffffffu, s, off);
        float inv = 1.f / s;
        float* op = g_attn + ((long)(b * NHEAD + hh) * HDIM + r) * HDIM;
        op[lane] = e0 * inv;
        if (lane + 32 < HDIM) op[lane + 32] = e1 * inv;
    }
}

// Mb rounded to tf32 values at write (GEMM2 A operand)
__global__ void k_mb(const float* __restrict__ wproj)
{
    int d = blockIdx.x, b = blockIdx.y, e = threadIdx.x;
    int hh = d / HDIM, dl = d % HDIM;
    __shared__ float acol[HDIM];
    if (e < HDIM) acol[e] = g_attn[((long)(b * NHEAD + hh) * HDIM + e) * HDIM + dl];
    __syncthreads();
    const float* wp = wproj + e * CH + hh * HDIM;
    float s = 0.f;
    #pragma unroll
    for (int c = 0; c < HDIM; c++) s += wp[c] * acol[c];
    g_mb[((long)(b * CH + e)) * CH + d] = f2tf_f(s);
}

// ---------------- launch ----------------
extern "C" void kernel_launch(void* const* d_in, const int* in_sizes, int n_in,
                              void* d_out, int out_size)
{
    const float* x     = (const float*)d_in[0];
    const float* Wqkv  = (const float*)d_in[1];
    const float* Wdw   = (const float*)d_in[2];
    const float* Whog  = (const float*)d_in[3];
    const float* Wproj = (const float*)d_in[4];
    const float* temp  = (const float*)d_in[5];
    float* out = (float*)d_out;

    float *p_qkv, *p_qkvd, *p_mb, *p_xr, *p_wr;
    cudaGetSymbolAddress((void**)&p_qkv,  g_qkv);
    cudaGetSymbolAddress((void**)&p_qkvd, g_qkvd);
    cudaGetSymbolAddress((void**)&p_mb,   g_mb);
    cudaGetSymbolAddress((void**)&p_xr,   g_xr);
    cudaGetSymbolAddress((void**)&p_wr,   g_wr);

    cudaFuncSetAttribute(k_gemm_tf32, cudaFuncAttributeMaxDynamicSharedMemorySize, GEMM_SMEM);

    // launches 0-2 (GEMM1 stays at capture index 3)
    k_sobel_part<<<dim3(8, BATCH, CGRP), 128>>>(x);   // also writes g_xr (rounded x)
    k_round<<<(C3 * CH) / 4 / 256, 256>>>((const float4*)Wqkv, (float4*)p_wr);
    k_hogbin<<<dim3(HH, BATCH), WW>>>();

    // launch 3: QKV 1x1 conv (tf32 mma, GBK=48, 3-stage cp.async)
    k_gemm_tf32<<<dim3(NPIX / GBN, C3 / GBM, BATCH), 256, GEMM_SMEM>>>(
        p_wr, p_xr, p_qkv, C3, CH, NPIX,
        0L, (long)CH * NPIX, (long)C3 * NPIX);

    // depthwise 3x3 + HOG add + norm partials (v rounded at write)
    k_dwconv<<<dim3(4, C3, BATCH), 128>>>(Wdw, Whog);

    // finalize q/k norms
    k_norm2<<<dim3(2 * CH, BATCH), 32>>>();

    // S partials
    k_spart<<<dim3(NSPLIT, NHEAD, BATCH), 256>>>();

    // softmax
    k_softmax<<<dim3(NHEAD, BATCH), 256>>>(temp);

    // Mb = W_proj @ blockdiag(attn)  (rounded at write)
    k_mb<<<dim3(CH, BATCH), CH>>>(Wproj);

    // out = Mb @ v (tf32 mma, GBK=48)
    k_gemm_tf32<<<dim3(NPIX / GBN, CH / GBM, BATCH), 256, GEMM_SMEM>>>(
        p_mb, p_qkvd + (long)2 * CH * NPIX, out, CH, CH, NPIX,
        (long)CH * CH, (long)C3 * NPIX, (long)CH * NPIX);
}